// round 16
// baseline (speedup 1.0000x reference)
#include <cuda_runtime.h>
#include <stdint.h>

#define BLOCK_SIZE 64
#define NUM_SELECTED 16
#define NB 128          // blocks per batch (8192/64)
#define B 32
#define D 512
#define S 8192

#define SEG_PER_BLK 4
#define THREADS 256
// float4 per block: 64*512/4 = 8192 ; per segment: 2048 ; per thread: 8
#define F4_PER_SEG ((BLOCK_SIZE * D / 4) / SEG_PER_BLK)
#define F4_PER_THREAD (F4_PER_SEG / THREADS)

// Converged fused design (see 15-round session ledger); this round's single
// delta: output stores use write-through (__stwt) so the 64 MB write stream
// does not write-allocate in L2, leaving L2 capacity to the key read stream.
// Exact jax.lax.top_k ordering: descending value, ties -> lower index.
// grid = B * NUM_SELECTED * SEG_PER_BLK = 2048 CTAs.
__global__ void __launch_bounds__(THREADS)
fused_gather_kernel(const float4* __restrict__ keys,
                    const float4* __restrict__ scores4,
                    float4* __restrict__ out) {
    int cta = blockIdx.x;
    int seg = cta & (SEG_PER_BLK - 1);
    int bk  = cta >> 2;                 // 0..511  (b*16 + k)
    int b   = bk >> 4;
    int k   = bk & (NUM_SELECTED - 1);

    __shared__ float4 s4[NB / 4];
    __shared__ int blk_s;
    int t = threadIdx.x;

    if (t < NB / 4) s4[t] = __ldg(&scores4[b * (NB / 4) + t]);
    __syncthreads();

    // Rank of score t among the batch's 128 block scores (vectorized).
    if (t < NB) {
        float v = ((const float*)s4)[t];
        int rank = 0;
#pragma unroll
        for (int j4 = 0; j4 < NB / 4; j4++) {
            float4 sj = s4[j4];
            int j = j4 * 4;
            rank += (sj.x > v) || (sj.x == v && (j + 0) < t);
            rank += (sj.y > v) || (sj.y == v && (j + 1) < t);
            rank += (sj.z > v) || (sj.z == v && (j + 2) < t);
            rank += (sj.w > v) || (sj.w == v && (j + 3) < t);
        }
        if (rank == k) blk_s = t;
    }
    __syncthreads();
    int blk = blk_s;

    const float4* src = keys
        + ((size_t)b * S + (size_t)blk * BLOCK_SIZE) * (D / 4)
        + (size_t)seg * F4_PER_SEG;
    float4* dst = out
        + (size_t)bk * (BLOCK_SIZE * D / 4)
        + (size_t)seg * F4_PER_SEG;

    // 8 float4 per thread, front-batched plain loads; write-through stores.
    float4 v[F4_PER_THREAD];
#pragma unroll
    for (int i = 0; i < F4_PER_THREAD; i++)
        v[i] = src[t + i * THREADS];
#pragma unroll
    for (int i = 0; i < F4_PER_THREAD; i++)
        __stwt(&dst[t + i * THREADS], v[i]);
}

extern "C" void kernel_launch(void* const* d_in, const int* in_sizes, int n_in,
                              void* d_out, int out_size) {
    const float* keys = (const float*)d_in[0];
    const float* scores = (const float*)d_in[1];
    float* out = (float*)d_out;

    fused_gather_kernel<<<B * NUM_SELECTED * SEG_PER_BLK, THREADS>>>(
        (const float4*)keys, (const float4*)scores, (float4*)out);
}

// round 17
// speedup vs baseline: 1.0445x; 1.0445x over previous
#include <cuda_runtime.h>
#include <stdint.h>

#define BLOCK_SIZE 64
#define NUM_SELECTED 16
#define NB 128          // blocks per batch (8192/64)
#define B 32
#define D 512
#define S 8192

#define SEG_PER_BLK 4
#define THREADS 256
// float4 per block: 64*512/4 = 8192 ; per segment: 2048 ; per thread: 8
#define F4_PER_SEG ((BLOCK_SIZE * D / 4) / SEG_PER_BLK)
#define F4_PER_THREAD (F4_PER_SEG / THREADS)

// FINAL — converged optimum over a 16-round session (29.2 -> 23.0 us).
// At the mixed-RW memory roofline: ~134 MB mandatory R+W at ~6.4 TB/s
// combined (~80% of HBM spec); no instruction-side pipe above ~50%.
// Tested & rejected at wall: split launch (+7us gap), PDL (+2.3us), TMA
// bulk (neutral), .cs hints (neutral), .wt stores (-wall), 16-deep MLP
// (reg spill to 74), single-wave 1024-CTA grid (slower), atomic handoff
// (equal), software pipelining (neutral).
//
// Design: fused, dependency-free. Each CTA recomputes the top-k rank for
// its own (b, k) from the batch's 128 block scores (16 KB total, L2-hot),
// then copies its contiguous 32 KB segment with 8 front-batched float4
// loads/stores per thread (regs 32, 8 CTAs/SM, occ ~80-90%).
// Exact jax.lax.top_k ordering: descending value, ties -> lower index.
// grid = B * NUM_SELECTED * SEG_PER_BLK = 2048 CTAs.
__global__ void __launch_bounds__(THREADS)
fused_gather_kernel(const float4* __restrict__ keys,
                    const float4* __restrict__ scores4,
                    float4* __restrict__ out) {
    int cta = blockIdx.x;
    int seg = cta & (SEG_PER_BLK - 1);
    int bk  = cta >> 2;                 // 0..511  (b*16 + k)
    int b   = bk >> 4;
    int k   = bk & (NUM_SELECTED - 1);

    __shared__ float4 s4[NB / 4];
    __shared__ int blk_s;
    int t = threadIdx.x;

    if (t < NB / 4) s4[t] = __ldg(&scores4[b * (NB / 4) + t]);
    __syncthreads();

    // Rank of score t among the batch's 128 block scores (vectorized).
    if (t < NB) {
        float v = ((const float*)s4)[t];
        int rank = 0;
#pragma unroll
        for (int j4 = 0; j4 < NB / 4; j4++) {
            float4 sj = s4[j4];
            int j = j4 * 4;
            rank += (sj.x > v) || (sj.x == v && (j + 0) < t);
            rank += (sj.y > v) || (sj.y == v && (j + 1) < t);
            rank += (sj.z > v) || (sj.z == v && (j + 2) < t);
            rank += (sj.w > v) || (sj.w == v && (j + 3) < t);
        }
        if (rank == k) blk_s = t;
    }
    __syncthreads();
    int blk = blk_s;

    const float4* src = keys
        + ((size_t)b * S + (size_t)blk * BLOCK_SIZE) * (D / 4)
        + (size_t)seg * F4_PER_SEG;
    float4* dst = out
        + (size_t)bk * (BLOCK_SIZE * D / 4)
        + (size_t)seg * F4_PER_SEG;

    // 8 float4 per thread, front-batched, plain loads/stores.
    float4 v[F4_PER_THREAD];
#pragma unroll
    for (int i = 0; i < F4_PER_THREAD; i++)
        v[i] = src[t + i * THREADS];
#pragma unroll
    for (int i = 0; i < F4_PER_THREAD; i++)
        dst[t + i * THREADS] = v[i];
}

extern "C" void kernel_launch(void* const* d_in, const int* in_sizes, int n_in,
                              void* d_out, int out_size) {
    const float* keys = (const float*)d_in[0];
    const float* scores = (const float*)d_in[1];
    float* out = (float*)d_out;

    fused_gather_kernel<<<B * NUM_SELECTED * SEG_PER_BLK, THREADS>>>(
        (const float4*)keys, (const float4*)scores, (float4*)out);
}